// round 15
// baseline (speedup 1.0000x reference)
#include <cuda_runtime.h>
#include <cuda_fp16.h>
#include <cstdint>

// ---------------------------------------------------------------------------
// Problem dims
// ---------------------------------------------------------------------------
#define B_   32
#define N_   2048
#define F_   1024
#define HS_  8192
#define HF_  4096
#define M1_  (B_ * F_)   // 32768
#define M2_  (B_ * N_)   // 65536
#define OUT_ 1024

// ---------------------------------------------------------------------------
// Device-global scratch
// ---------------------------------------------------------------------------
constexpr size_t SZ_XS  = (size_t)M1_ * N_;
constexpr size_t SZ_H   = (size_t)M1_ * HS_;
constexpr size_t SZ_Y2  = (size_t)M2_ * F_;
constexpr size_t SZ_H2  = (size_t)M2_ * HF_;
constexpr size_t SZ_SW1 = (size_t)HS_ * N_;
constexpr size_t SZ_SW2 = (size_t)N_ * HS_;
constexpr size_t SZ_FW1 = (size_t)HF_ * F_;
constexpr size_t SZ_FW2 = (size_t)OUT_ * HF_;

__device__ __half g_xs[SZ_XS];          // single fp16 activation (GEMM A)
__device__ __half g_xs_lo[SZ_XS];       // lo limb kept ONLY for skip-add precision
__device__ unsigned short g_invp[SZ_XS];
__device__ __half g_h[SZ_H];
__device__ __half g_y2[SZ_Y2];
__device__ __half g_h2[SZ_H2];
__device__ __half g_sw1[SZ_SW1];
__device__ __half g_sw2[SZ_SW2];
__device__ __half g_fw1[SZ_FW1];
__device__ __half g_fw2[SZ_FW2];

// ---------------------------------------------------------------------------
// Helpers
// ---------------------------------------------------------------------------
__device__ __forceinline__ void split_h(float v, __half& h, __half& l) {
    h = __float2half_rn(v);
    l = __float2half_rn(v - __half2float(h));
}

__global__ __launch_bounds__(256) void round_kernel(const float* __restrict__ in,
                             __half* __restrict__ w, int n) {
    int i = blockIdx.x * 256 + threadIdx.x;
    if (i < n) w[i] = __float2half_rn(in[i]);
}

// ---------------------------------------------------------------------------
// Sort kernel (validated core)
// ---------------------------------------------------------------------------
__global__ __launch_bounds__(512) void sort_kernel(
    const float* __restrict__ x,
    __half* __restrict__ xs, __half* __restrict__ xs_lo,
    unsigned short* __restrict__ invp)
{
    __shared__ unsigned long long keys[N_];
    __shared__ float xorig[N_];
    __shared__ float xsv[N_];
    __shared__ unsigned short invs[N_];

    const int m = blockIdx.x;
    const int b = m >> 10;
    const int f = m & (F_ - 1);
    const float* xrow = x + ((size_t)b * N_) * F_ + f;

    for (int j = threadIdx.x; j < N_; j += 512) {
        float v = xrow[(size_t)j * F_];
        unsigned u = __float_as_uint(v);
        u = (u & 0x80000000u) ? ~u : (u | 0x80000000u);
        keys[j] = ((unsigned long long)u << 16) | (unsigned)j;
        xorig[j] = v;
    }
    __syncthreads();

    for (int k = 2; k <= N_; k <<= 1) {
        for (int j = k >> 1; j > 0; j >>= 1) {
            for (int t = threadIdx.x; t < N_ / 2; t += 512) {
                int i = ((t & ~(j - 1)) << 1) | (t & (j - 1));
                int l = i | j;
                bool up = ((i & k) == 0);
                unsigned long long a = keys[i], c = keys[l];
                if ((a > c) == up) { keys[i] = c; keys[l] = a; }
            }
            __syncthreads();
        }
    }

    for (int jslot = threadIdx.x; jslot < N_; jslot += 512) {
        int pj = (int)(keys[jslot] & 0xFFFFu);
        xsv[pj] = xorig[jslot];
        invs[pj] = (unsigned short)jslot;
    }
    __syncthreads();

    size_t base = (size_t)m * N_;
    for (int i = threadIdx.x; i < N_; i += 512) {
        __half h, l;
        split_h(xsv[i], h, l);
        xs[base + i] = h;
        xs_lo[base + i] = l;
        invp[base + i] = invs[i];
    }
}

// ---------------------------------------------------------------------------
// GEMM: C[M,N] = A[M,K] @ W[N,K]^T, fp16 in / fp32 accum mma.sync.
// CTA tile 128x256, BK=32, warp tile 64x64 (8 warps, 2x4), 6-stage cp.async
// (prefetch 5), conflict-free swizzle, 1 CTA/SM.
// ---------------------------------------------------------------------------
__device__ __forceinline__ void cp16(unsigned s, const void* g) {
    asm volatile("cp.async.cg.shared.global [%0], [%1], 16;\n" :: "r"(s), "l"(g) : "memory");
}
__device__ __forceinline__ void cp_commit() {
    asm volatile("cp.async.commit_group;\n" ::: "memory");
}
template <int Np>
__device__ __forceinline__ void cp_waitg() {
    asm volatile("cp.async.wait_group %0;\n" :: "n"(Np) : "memory");
}
__device__ __forceinline__ void ldsm4(unsigned* r, unsigned addr) {
    asm volatile("ldmatrix.sync.aligned.m8n8.x4.shared.b16 {%0,%1,%2,%3}, [%4];\n"
        : "=r"(r[0]), "=r"(r[1]), "=r"(r[2]), "=r"(r[3]) : "r"(addr));
}
__device__ __forceinline__ void mma_f16(float* c, const unsigned* a, const unsigned* b) {
    asm volatile(
        "mma.sync.aligned.m16n8k16.row.col.f32.f16.f16.f32 "
        "{%0,%1,%2,%3}, {%4,%5,%6,%7}, {%8,%9}, {%0,%1,%2,%3};\n"
        : "+f"(c[0]), "+f"(c[1]), "+f"(c[2]), "+f"(c[3])
        : "r"(a[0]), "r"(a[1]), "r"(a[2]), "r"(a[3]), "r"(b[0]), "r"(b[1]));
}

// stage: A 8KB (128 rows x 64B) | W 16KB (256 rows x 64B)
#define SS_      24576
#define A_OFF    0
#define W_OFF    8192
#define NSTAGE   6
#define PREF     5
#define SMEM_BYTES (NSTAGE * SS_)   // 147456

// Conflict-free swizzle: chunk ^= (row>>1)&3 within 64B rows.
__device__ __forceinline__ unsigned sw_off(int row, int clog) {
    return (unsigned)(row * 64 + ((clog ^ ((row >> 1) & 3)) << 4));
}

__device__ __forceinline__ void stage_load(
    unsigned sst,
    const __half* __restrict__ A, const __half* __restrict__ W,
    int m0, int n0, int K, int k0, int tid)
{
#pragma unroll
    for (int it = 0; it < 6; it++) {       // 1536 chunks / 256 threads
        int c = tid + it * 256;
        if (c < 512) {                     // A: 128 rows x 4 chunks
            int row = c >> 2, clog = c & 3;
            cp16(sst + A_OFF + sw_off(row, clog),
                 A + (size_t)(m0 + row) * K + k0 + clog * 8);
        } else {                           // W: 256 rows x 4 chunks
            int cw = c - 512;
            int row = cw >> 2, clog = cw & 3;
            cp16(sst + W_OFF + sw_off(row, clog),
                 W + (size_t)(n0 + row) * K + k0 + clog * 8);
        }
    }
}

// EPI: 0 = bias+relu -> fp16; 1 = bias+skip(hi+lo)+unsort-scatter -> fp16;
//      3 = bias -> fp32
template <int EPI>
__global__ __launch_bounds__(256, 1) void gemm_kernel(
    int M, int Nn, int K,
    const __half* __restrict__ A, const __half* __restrict__ W,
    const float* __restrict__ bias,
    __half* __restrict__ Oh, float* __restrict__ Of,
    const __half* __restrict__ Sh, const __half* __restrict__ Sl,
    const unsigned short* __restrict__ invp)
{
    extern __shared__ __half smem[];
    const int tid = threadIdx.x;
    const int m0 = blockIdx.y * 128;
    const int n0 = blockIdx.x * 256;
    const unsigned sbase = (unsigned)__cvta_generic_to_shared(smem);

    float acc[4][8][4];
#pragma unroll
    for (int a = 0; a < 4; a++)
#pragma unroll
        for (int b = 0; b < 8; b++)
#pragma unroll
            for (int e = 0; e < 4; e++) acc[a][b][e] = 0.f;

    const int nk = K >> 5;
    const int lane = tid & 31;
    const int wid = tid >> 5;
    const int wm = wid >> 2;   // 0..1 -> 64 rows
    const int wn = wid & 3;    // 0..3 -> 64 cols

    // prologue: PREF stages in flight
#pragma unroll
    for (int s = 0; s < PREF; s++) {
        stage_load(sbase + s * SS_, A, W, m0, n0, K, s * 32, tid);
        cp_commit();
    }

    for (int kt = 0; kt < nk; kt++) {
        cp_waitg<PREF - 1>();
        __syncthreads();

        const unsigned sst = sbase + (kt % NSTAGE) * SS_;
#pragma unroll
        for (int step = 0; step < 2; step++) {
            unsigned a_r[4][4], w_r[4][4];
            // A fragments: rows wm*64 + mt*16 + (lane&15), k-group per lane>>4
            const int arow = lane & 15;
            const int ag = step * 2 + (lane >> 4);
#pragma unroll
            for (int mt = 0; mt < 4; mt++) {
                int row = wm * 64 + mt * 16 + arow;
                ldsm4(a_r[mt], sst + A_OFF + sw_off(row, ag));
            }
            // W fragments: ldsm4 covers two n-tiles (16 n-rows) x k16.
            // lane groups: 0-7: n0-7 klo | 8-15: n0-7 khi | 16-23: n8-15 klo | 24-31: n8-15 khi
            const int wrow_in = ((lane >> 4) << 3) + (lane & 7);
            const int wg = step * 2 + ((lane >> 3) & 1);
#pragma unroll
            for (int ntp = 0; ntp < 4; ntp++) {
                int row = wn * 64 + ntp * 16 + wrow_in;
                ldsm4(w_r[ntp], sst + W_OFF + sw_off(row, wg));
            }
#pragma unroll
            for (int ntp = 0; ntp < 4; ntp++)
#pragma unroll
                for (int half = 0; half < 2; half++) {
                    const unsigned* bfr = &w_r[ntp][half * 2];
                    const int nt = ntp * 2 + half;
#pragma unroll
                    for (int mt = 0; mt < 4; mt++)
                        mma_f16(acc[mt][nt], a_r[mt], bfr);
                }
        }

        if (kt + PREF < nk)
            stage_load(sbase + ((kt + PREF) % NSTAGE) * SS_, A, W,
                       m0, n0, K, (kt + PREF) * 32, tid);
        cp_commit();
    }

    // ---------------- epilogue ----------------
    const int quad = lane >> 2;
    const int qt = (lane & 3) << 1;
#pragma unroll
    for (int mt = 0; mt < 4; mt++) {
#pragma unroll
        for (int nt = 0; nt < 8; nt++) {
#pragma unroll
            for (int eh = 0; eh < 2; eh++) {
                int m = m0 + wm * 64 + mt * 16 + quad + eh * 8;
                int n = n0 + wn * 64 + nt * 8 + qt;
                float v0 = acc[mt][nt][eh * 2 + 0] + bias[n];
                float v1 = acc[mt][nt][eh * 2 + 1] + bias[n + 1];
                if (EPI == 0) {
                    v0 = fmaxf(v0, 0.f); v1 = fmaxf(v1, 0.f);
                    size_t o = (size_t)m * Nn + n;
                    *(__half2*)(Oh + o) =
                        __halves2half2(__float2half_rn(v0), __float2half_rn(v1));
                } else if (EPI == 1) {
#pragma unroll
                    for (int e = 0; e < 2; e++) {
                        float v = (e == 0) ? v0 : v1;
                        int nn = n + e;
                        size_t si = (size_t)m * Nn + nn;
                        v += __half2float(Sh[si]) + __half2float(Sl[si]);
                        int bb = m >> 10;            // m = b*F + f
                        int f  = m & (F_ - 1);
                        int np = invp[si];
                        size_t o = ((size_t)(bb * N_ + np)) * F_ + f;
                        Oh[o] = __float2half_rn(v);
                    }
                } else {  // EPI == 3
                    *(float2*)(Of + (size_t)m * Nn + n) = make_float2(v0, v1);
                }
            }
        }
    }
}

// ---------------------------------------------------------------------------
// Launch
// ---------------------------------------------------------------------------
extern "C" void kernel_launch(void* const* d_in, const int* in_sizes, int n_in,
                              void* d_out, int out_size) {
    const float* x   = (const float*)d_in[0];
    const float* sw1 = (const float*)d_in[1];
    const float* sb1 = (const float*)d_in[2];
    const float* sw2 = (const float*)d_in[3];
    const float* sb2 = (const float*)d_in[4];
    const float* fw1 = (const float*)d_in[5];
    const float* fb1 = (const float*)d_in[6];
    const float* fw2 = (const float*)d_in[7];
    const float* fb2 = (const float*)d_in[8];
    float* out = (float*)d_out;

    void *p_xs, *p_xs_lo, *p_invp, *p_h, *p_y2, *p_h2,
         *p_sw1, *p_sw2, *p_fw1, *p_fw2;
    cudaGetSymbolAddress(&p_xs,    g_xs);
    cudaGetSymbolAddress(&p_xs_lo, g_xs_lo);
    cudaGetSymbolAddress(&p_invp,  g_invp);
    cudaGetSymbolAddress(&p_h,     g_h);
    cudaGetSymbolAddress(&p_y2,    g_y2);
    cudaGetSymbolAddress(&p_h2,    g_h2);
    cudaGetSymbolAddress(&p_sw1,   g_sw1);
    cudaGetSymbolAddress(&p_sw2,   g_sw2);
    cudaGetSymbolAddress(&p_fw1,   g_fw1);
    cudaGetSymbolAddress(&p_fw2,   g_fw2);

    cudaFuncSetAttribute(gemm_kernel<0>, cudaFuncAttributeMaxDynamicSharedMemorySize, SMEM_BYTES);
    cudaFuncSetAttribute(gemm_kernel<1>, cudaFuncAttributeMaxDynamicSharedMemorySize, SMEM_BYTES);
    cudaFuncSetAttribute(gemm_kernel<3>, cudaFuncAttributeMaxDynamicSharedMemorySize, SMEM_BYTES);

    round_kernel<<<(int)((SZ_SW1 + 255) / 256), 256>>>(sw1, (__half*)p_sw1, (int)SZ_SW1);
    round_kernel<<<(int)((SZ_SW2 + 255) / 256), 256>>>(sw2, (__half*)p_sw2, (int)SZ_SW2);
    round_kernel<<<(int)((SZ_FW1 + 255) / 256), 256>>>(fw1, (__half*)p_fw1, (int)SZ_FW1);
    round_kernel<<<(int)((SZ_FW2 + 255) / 256), 256>>>(fw2, (__half*)p_fw2, (int)SZ_FW2);

    sort_kernel<<<M1_, 512>>>(x, (__half*)p_xs, (__half*)p_xs_lo,
                              (unsigned short*)p_invp);

    // G1: H = relu(Xs @ sw1^T + sb1)   [M1, HS]
    {
        dim3 g(HS_ / 256, M1_ / 128);
        gemm_kernel<0><<<g, 256, SMEM_BYTES>>>(
            M1_, HS_, N_,
            (__half*)p_xs, (__half*)p_sw1, sb1,
            (__half*)p_h, nullptr,
            nullptr, nullptr, nullptr);
    }
    // G2: Y = H @ sw2^T + sb2 + Xs(hi+lo), unsort+transpose-scatter -> Y2[B,N,F]
    {
        dim3 g(N_ / 256, M1_ / 128);
        gemm_kernel<1><<<g, 256, SMEM_BYTES>>>(
            M1_, N_, HS_,
            (__half*)p_h, (__half*)p_sw2, sb2,
            (__half*)p_y2, nullptr,
            (__half*)p_xs, (__half*)p_xs_lo,
            (const unsigned short*)p_invp);
    }
    // G3: H2 = relu(Y2 @ fw1^T + fb1)  [M2, HF]
    {
        dim3 g(HF_ / 256, M2_ / 128);
        gemm_kernel<0><<<g, 256, SMEM_BYTES>>>(
            M2_, HF_, F_,
            (__half*)p_y2, (__half*)p_fw1, fb1,
            (__half*)p_h2, nullptr,
            nullptr, nullptr, nullptr);
    }
    // G4: out = H2 @ fw2^T + fb2       [M2, OUT] fp32
    {
        dim3 g(OUT_ / 256, M2_ / 128);
        gemm_kernel<3><<<g, 256, SMEM_BYTES>>>(
            M2_, OUT_, HF_,
            (__half*)p_h2, (__half*)p_fw2, fb2,
            nullptr, out,
            nullptr, nullptr, nullptr);
    }
}

// round 16
// speedup vs baseline: 1.1321x; 1.1321x over previous
#include <cuda_runtime.h>
#include <cuda_fp16.h>
#include <cstdint>

// ---------------------------------------------------------------------------
// Problem dims
// ---------------------------------------------------------------------------
#define B_   32
#define N_   2048
#define F_   1024
#define HS_  8192
#define HF_  4096
#define M1_  (B_ * F_)   // 32768
#define M2_  (B_ * N_)   // 65536
#define OUT_ 1024

// ---------------------------------------------------------------------------
// Device-global scratch
// ---------------------------------------------------------------------------
constexpr size_t SZ_XS  = (size_t)M1_ * N_;
constexpr size_t SZ_H   = (size_t)M1_ * HS_;
constexpr size_t SZ_Y2  = (size_t)M2_ * F_;
constexpr size_t SZ_H2  = (size_t)M2_ * HF_;
constexpr size_t SZ_SW1 = (size_t)HS_ * N_;
constexpr size_t SZ_SW2 = (size_t)N_ * HS_;
constexpr size_t SZ_FW1 = (size_t)HF_ * F_;
constexpr size_t SZ_FW2 = (size_t)OUT_ * HF_;

__device__ __half g_xs[SZ_XS];          // single fp16 activation (GEMM A)
__device__ __half g_xs_lo[SZ_XS];       // lo limb kept ONLY for skip-add precision
__device__ unsigned short g_invp[SZ_XS];
__device__ __half g_h[SZ_H];
__device__ __half g_y2[SZ_Y2];
__device__ __half g_h2[SZ_H2];
__device__ __half g_sw1[SZ_SW1];
__device__ __half g_sw2[SZ_SW2];
__device__ __half g_fw1[SZ_FW1];
__device__ __half g_fw2[SZ_FW2];

// ---------------------------------------------------------------------------
// Helpers
// ---------------------------------------------------------------------------
__device__ __forceinline__ void split_h(float v, __half& h, __half& l) {
    h = __float2half_rn(v);
    l = __float2half_rn(v - __half2float(h));
}

__global__ __launch_bounds__(256) void round_kernel(const float* __restrict__ in,
                             __half* __restrict__ w, int n) {
    int i = blockIdx.x * 256 + threadIdx.x;
    if (i < n) w[i] = __float2half_rn(in[i]);
}

// ---------------------------------------------------------------------------
// Sort kernel (validated core)
// ---------------------------------------------------------------------------
__global__ __launch_bounds__(512) void sort_kernel(
    const float* __restrict__ x,
    __half* __restrict__ xs, __half* __restrict__ xs_lo,
    unsigned short* __restrict__ invp)
{
    __shared__ unsigned long long keys[N_];
    __shared__ float xorig[N_];
    __shared__ float xsv[N_];
    __shared__ unsigned short invs[N_];

    const int m = blockIdx.x;
    const int b = m >> 10;
    const int f = m & (F_ - 1);
    const float* xrow = x + ((size_t)b * N_) * F_ + f;

    for (int j = threadIdx.x; j < N_; j += 512) {
        float v = xrow[(size_t)j * F_];
        unsigned u = __float_as_uint(v);
        u = (u & 0x80000000u) ? ~u : (u | 0x80000000u);
        keys[j] = ((unsigned long long)u << 16) | (unsigned)j;
        xorig[j] = v;
    }
    __syncthreads();

    for (int k = 2; k <= N_; k <<= 1) {
        for (int j = k >> 1; j > 0; j >>= 1) {
            for (int t = threadIdx.x; t < N_ / 2; t += 512) {
                int i = ((t & ~(j - 1)) << 1) | (t & (j - 1));
                int l = i | j;
                bool up = ((i & k) == 0);
                unsigned long long a = keys[i], c = keys[l];
                if ((a > c) == up) { keys[i] = c; keys[l] = a; }
            }
            __syncthreads();
        }
    }

    for (int jslot = threadIdx.x; jslot < N_; jslot += 512) {
        int pj = (int)(keys[jslot] & 0xFFFFu);
        xsv[pj] = xorig[jslot];
        invs[pj] = (unsigned short)jslot;
    }
    __syncthreads();

    size_t base = (size_t)m * N_;
    for (int i = threadIdx.x; i < N_; i += 512) {
        __half h, l;
        split_h(xsv[i], h, l);
        xs[base + i] = h;
        xs_lo[base + i] = l;
        invp[base + i] = invs[i];
    }
}

// ---------------------------------------------------------------------------
// GEMM: C[M,N] = A[M,K] @ W[N,K]^T, fp16 in / fp32 accum mma.sync.
// CTA tile 128x128, 4 warps (2x2), warp tile 64x64, BK=32, 6-stage cp.async
// (prefetch 5), conflict-free swizzle, 2 CTAs/SM.
// ---------------------------------------------------------------------------
__device__ __forceinline__ void cp16(unsigned s, const void* g) {
    asm volatile("cp.async.cg.shared.global [%0], [%1], 16;\n" :: "r"(s), "l"(g) : "memory");
}
__device__ __forceinline__ void cp_commit() {
    asm volatile("cp.async.commit_group;\n" ::: "memory");
}
template <int Np>
__device__ __forceinline__ void cp_waitg() {
    asm volatile("cp.async.wait_group %0;\n" :: "n"(Np) : "memory");
}
__device__ __forceinline__ void ldsm4(unsigned* r, unsigned addr) {
    asm volatile("ldmatrix.sync.aligned.m8n8.x4.shared.b16 {%0,%1,%2,%3}, [%4];\n"
        : "=r"(r[0]), "=r"(r[1]), "=r"(r[2]), "=r"(r[3]) : "r"(addr));
}
__device__ __forceinline__ void mma_f16(float* c, const unsigned* a, const unsigned* b) {
    asm volatile(
        "mma.sync.aligned.m16n8k16.row.col.f32.f16.f16.f32 "
        "{%0,%1,%2,%3}, {%4,%5,%6,%7}, {%8,%9}, {%0,%1,%2,%3};\n"
        : "+f"(c[0]), "+f"(c[1]), "+f"(c[2]), "+f"(c[3])
        : "r"(a[0]), "r"(a[1]), "r"(a[2]), "r"(a[3]), "r"(b[0]), "r"(b[1]));
}

// stage: A 8KB (128 rows x 64B) | W 8KB (128 rows x 64B)
#define SS_      16384
#define A_OFF    0
#define W_OFF    8192
#define NSTAGE   6
#define PREF     5
#define SMEM_BYTES (NSTAGE * SS_)   // 98304 per CTA; x2 CTAs = 192KB/SM

#define NTHREADS 128

// Conflict-free swizzle: chunk ^= (row>>1)&3 within 64B rows.
__device__ __forceinline__ unsigned sw_off(int row, int clog) {
    return (unsigned)(row * 64 + ((clog ^ ((row >> 1) & 3)) << 4));
}

__device__ __forceinline__ void stage_load(
    unsigned sst,
    const __half* __restrict__ A, const __half* __restrict__ W,
    int m0, int n0, int K, int k0, int tid)
{
#pragma unroll
    for (int it = 0; it < 8; it++) {       // 1024 chunks / 128 threads
        int c = tid + it * NTHREADS;
        int arr = c >> 9;                  // 0:A 1:W
        int cc = c & 511;
        int row = cc >> 2, clog = cc & 3;
        unsigned dst = sst + arr * 8192 + sw_off(row, clog);
        const __half* base = arr ? W : A;
        int r0 = arr ? n0 : m0;
        cp16(dst, base + (size_t)(r0 + row) * K + k0 + clog * 8);
    }
}

// EPI: 0 = bias+relu -> fp16; 1 = bias+skip(hi+lo)+unsort-scatter -> fp16;
//      3 = bias -> fp32
template <int EPI>
__global__ __launch_bounds__(NTHREADS, 2) void gemm_kernel(
    int M, int Nn, int K,
    const __half* __restrict__ A, const __half* __restrict__ W,
    const float* __restrict__ bias,
    __half* __restrict__ Oh, float* __restrict__ Of,
    const __half* __restrict__ Sh, const __half* __restrict__ Sl,
    const unsigned short* __restrict__ invp)
{
    extern __shared__ __half smem[];
    const int tid = threadIdx.x;
    const int m0 = blockIdx.y * 128;
    const int n0 = blockIdx.x * 128;
    const unsigned sbase = (unsigned)__cvta_generic_to_shared(smem);

    float acc[4][8][4];
#pragma unroll
    for (int a = 0; a < 4; a++)
#pragma unroll
        for (int b = 0; b < 8; b++)
#pragma unroll
            for (int e = 0; e < 4; e++) acc[a][b][e] = 0.f;

    const int nk = K >> 5;
    const int lane = tid & 31;
    const int wid = tid >> 5;    // 0..3
    const int wm = wid >> 1;     // 0..1 -> 64 rows
    const int wn = wid & 1;      // 0..1 -> 64 cols

    // prologue: PREF stages in flight
#pragma unroll
    for (int s = 0; s < PREF; s++) {
        stage_load(sbase + s * SS_, A, W, m0, n0, K, s * 32, tid);
        cp_commit();
    }

    for (int kt = 0; kt < nk; kt++) {
        cp_waitg<PREF - 1>();
        __syncthreads();

        const unsigned sst = sbase + (kt % NSTAGE) * SS_;
#pragma unroll
        for (int step = 0; step < 2; step++) {
            unsigned a_r[4][4], w_r[4][4];
            // A fragments
            const int arow = lane & 15;
            const int ag = step * 2 + (lane >> 4);
#pragma unroll
            for (int mt = 0; mt < 4; mt++) {
                int row = wm * 64 + mt * 16 + arow;
                ldsm4(a_r[mt], sst + A_OFF + sw_off(row, ag));
            }
            // W fragments: ldsm4 covers two n-tiles (16 n-rows) x k16
            // lanes 0-7: n0-7 klo | 8-15: n0-7 khi | 16-23: n8-15 klo | 24-31: n8-15 khi
            const int wrow_in = ((lane >> 4) << 3) + (lane & 7);
            const int wg = step * 2 + ((lane >> 3) & 1);
#pragma unroll
            for (int ntp = 0; ntp < 4; ntp++) {
                int row = wn * 64 + ntp * 16 + wrow_in;
                ldsm4(w_r[ntp], sst + W_OFF + sw_off(row, wg));
            }
#pragma unroll
            for (int ntp = 0; ntp < 4; ntp++)
#pragma unroll
                for (int half = 0; half < 2; half++) {
                    const unsigned* bfr = &w_r[ntp][half * 2];
                    const int nt = ntp * 2 + half;
#pragma unroll
                    for (int mt = 0; mt < 4; mt++)
                        mma_f16(acc[mt][nt], a_r[mt], bfr);
                }
        }

        if (kt + PREF < nk)
            stage_load(sbase + ((kt + PREF) % NSTAGE) * SS_, A, W,
                       m0, n0, K, (kt + PREF) * 32, tid);
        cp_commit();
    }

    // ---------------- epilogue ----------------
    const int quad = lane >> 2;
    const int qt = (lane & 3) << 1;
#pragma unroll
    for (int mt = 0; mt < 4; mt++) {
#pragma unroll
        for (int nt = 0; nt < 8; nt++) {
#pragma unroll
            for (int eh = 0; eh < 2; eh++) {
                int m = m0 + wm * 64 + mt * 16 + quad + eh * 8;
                int n = n0 + wn * 64 + nt * 8 + qt;
                float v0 = acc[mt][nt][eh * 2 + 0] + bias[n];
                float v1 = acc[mt][nt][eh * 2 + 1] + bias[n + 1];
                if (EPI == 0) {
                    v0 = fmaxf(v0, 0.f); v1 = fmaxf(v1, 0.f);
                    size_t o = (size_t)m * Nn + n;
                    *(__half2*)(Oh + o) =
                        __halves2half2(__float2half_rn(v0), __float2half_rn(v1));
                } else if (EPI == 1) {
#pragma unroll
                    for (int e = 0; e < 2; e++) {
                        float v = (e == 0) ? v0 : v1;
                        int nn = n + e;
                        size_t si = (size_t)m * Nn + nn;
                        v += __half2float(Sh[si]) + __half2float(Sl[si]);
                        int bb = m >> 10;            // m = b*F + f
                        int f  = m & (F_ - 1);
                        int np = invp[si];
                        size_t o = ((size_t)(bb * N_ + np)) * F_ + f;
                        Oh[o] = __float2half_rn(v);
                    }
                } else {  // EPI == 3
                    *(float2*)(Of + (size_t)m * Nn + n) = make_float2(v0, v1);
                }
            }
        }
    }
}

// ---------------------------------------------------------------------------
// Launch
// ---------------------------------------------------------------------------
extern "C" void kernel_launch(void* const* d_in, const int* in_sizes, int n_in,
                              void* d_out, int out_size) {
    const float* x   = (const float*)d_in[0];
    const float* sw1 = (const float*)d_in[1];
    const float* sb1 = (const float*)d_in[2];
    const float* sw2 = (const float*)d_in[3];
    const float* sb2 = (const float*)d_in[4];
    const float* fw1 = (const float*)d_in[5];
    const float* fb1 = (const float*)d_in[6];
    const float* fw2 = (const float*)d_in[7];
    const float* fb2 = (const float*)d_in[8];
    float* out = (float*)d_out;

    void *p_xs, *p_xs_lo, *p_invp, *p_h, *p_y2, *p_h2,
         *p_sw1, *p_sw2, *p_fw1, *p_fw2;
    cudaGetSymbolAddress(&p_xs,    g_xs);
    cudaGetSymbolAddress(&p_xs_lo, g_xs_lo);
    cudaGetSymbolAddress(&p_invp,  g_invp);
    cudaGetSymbolAddress(&p_h,     g_h);
    cudaGetSymbolAddress(&p_y2,    g_y2);
    cudaGetSymbolAddress(&p_h2,    g_h2);
    cudaGetSymbolAddress(&p_sw1,   g_sw1);
    cudaGetSymbolAddress(&p_sw2,   g_sw2);
    cudaGetSymbolAddress(&p_fw1,   g_fw1);
    cudaGetSymbolAddress(&p_fw2,   g_fw2);

    cudaFuncSetAttribute(gemm_kernel<0>, cudaFuncAttributeMaxDynamicSharedMemorySize, SMEM_BYTES);
    cudaFuncSetAttribute(gemm_kernel<1>, cudaFuncAttributeMaxDynamicSharedMemorySize, SMEM_BYTES);
    cudaFuncSetAttribute(gemm_kernel<3>, cudaFuncAttributeMaxDynamicSharedMemorySize, SMEM_BYTES);

    round_kernel<<<(int)((SZ_SW1 + 255) / 256), 256>>>(sw1, (__half*)p_sw1, (int)SZ_SW1);
    round_kernel<<<(int)((SZ_SW2 + 255) / 256), 256>>>(sw2, (__half*)p_sw2, (int)SZ_SW2);
    round_kernel<<<(int)((SZ_FW1 + 255) / 256), 256>>>(fw1, (__half*)p_fw1, (int)SZ_FW1);
    round_kernel<<<(int)((SZ_FW2 + 255) / 256), 256>>>(fw2, (__half*)p_fw2, (int)SZ_FW2);

    sort_kernel<<<M1_, 512>>>(x, (__half*)p_xs, (__half*)p_xs_lo,
                              (unsigned short*)p_invp);

    // G1: H = relu(Xs @ sw1^T + sb1)   [M1, HS]
    {
        dim3 g(HS_ / 128, M1_ / 128);
        gemm_kernel<0><<<g, NTHREADS, SMEM_BYTES>>>(
            M1_, HS_, N_,
            (__half*)p_xs, (__half*)p_sw1, sb1,
            (__half*)p_h, nullptr,
            nullptr, nullptr, nullptr);
    }
    // G2: Y = H @ sw2^T + sb2 + Xs(hi+lo), unsort+transpose-scatter -> Y2[B,N,F]
    {
        dim3 g(N_ / 128, M1_ / 128);
        gemm_kernel<1><<<g, NTHREADS, SMEM_BYTES>>>(
            M1_, N_, HS_,
            (__half*)p_h, (__half*)p_sw2, sb2,
            (__half*)p_y2, nullptr,
            (__half*)p_xs, (__half*)p_xs_lo,
            (const unsigned short*)p_invp);
    }
    // G3: H2 = relu(Y2 @ fw1^T + fb1)  [M2, HF]
    {
        dim3 g(HF_ / 128, M2_ / 128);
        gemm_kernel<0><<<g, NTHREADS, SMEM_BYTES>>>(
            M2_, HF_, F_,
            (__half*)p_y2, (__half*)p_fw1, fb1,
            (__half*)p_h2, nullptr,
            nullptr, nullptr, nullptr);
    }
    // G4: out = H2 @ fw2^T + fb2       [M2, OUT] fp32
    {
        dim3 g(OUT_ / 128, M2_ / 128);
        gemm_kernel<3><<<g, NTHREADS, SMEM_BYTES>>>(
            M2_, OUT_, HF_,
            (__half*)p_h2, (__half*)p_fw2, fb2,
            nullptr, out,
            nullptr, nullptr, nullptr);
    }
}